// round 1
// baseline (speedup 1.0000x reference)
#include <cuda_runtime.h>
#include <cuda_bf16.h>
#include <math_constants.h>

#define B 16
#define N 8400
#define M 32
#define C 80
#define TOPK 13

// Output layout (f32 elements), tuple flattened & concatenated:
#define L0 0                      // target_labels  (B,N)
#define L1 (B*N)                  // target_bboxes  (B,N,4)
#define L2 (L1 + B*N*4)           // target_scores  (B,N,C)
#define L3 (L2 + B*N*C)           // fg_mask        (B,N)
#define L4 (L3 + B*N)             // target_gt_idx  (B,N)

// Scratch (device globals; no allocation at runtime)
__device__ float    g_align[B*M*N];
__device__ float    g_over [B*M*N];
__device__ unsigned g_maskpos[B*N];
__device__ float    g_posalign[B*M];
__device__ float    g_posover [B*M];
__device__ int      g_mask_is_u8;

__global__ void k_init(const unsigned char* mask_raw) {
    int i = blockIdx.x * blockDim.x + threadIdx.x;
    if (i < B*N) g_maskpos[i] = 0u;
    if (i < B*M) { g_posalign[i] = 0.f; g_posover[i] = 0.f; }
    if (i == 0) {
        // Detect whether mask_gt arrived as uint8 (bool) or int32.
        // Safe: reads only 512 bytes, which exist in either interpretation.
        int u8 = 0;
        for (int p = 0; p < B*M; p++)
            if ((p & 3) != 0 && mask_raw[p] != 0) u8 = 1;
        g_mask_is_u8 = u8;
    }
}

__global__ __launch_bounds__(256) void k_rows(
    const float* __restrict__ ps,      // pd_scores (B,N,C)
    const float* __restrict__ pb,      // pd_bboxes (B,N,4)
    const float* __restrict__ anc,     // anc_points (N,2)
    const int*   __restrict__ labels,  // gt_labels (B,M,1)
    const float* __restrict__ gtb,     // gt_bboxes (B,M,4)
    const void*  __restrict__ maskg)   // mask_gt (B,M,1)
{
    __shared__ float row[N];
    __shared__ float rv[256];
    __shared__ int   ri[256];
    __shared__ int   pick[TOPK];

    const int bm = blockIdx.x;      // b*M + m
    const int b  = bm >> 5;
    const int m  = bm & 31;
    const int t  = threadIdx.x;

    int mg = g_mask_is_u8 ? (int)((const unsigned char*)maskg)[bm]
                          : ((const int*)maskg)[bm];

    float* __restrict__ arow = g_align + (size_t)bm * N;
    float* __restrict__ orow = g_over  + (size_t)bm * N;

    if (!mg) {
        for (int n = t; n < N; n += 256) { arow[n] = 0.f; orow[n] = 0.f; }
        return;
    }

    const float4 gt = ((const float4*)gtb)[bm];
    const int cls = labels[bm];
    const float gx1 = gt.x, gy1 = gt.y, gx2 = gt.z, gy2 = gt.w;
    const float w1 = gx2 - gx1;
    const float h1 = gy2 - gy1 + 1e-7f;
    const float at1 = atanf(w1 / h1);
    const float inv_pi2_4 = 4.0f / (CUDART_PI_F * CUDART_PI_F);

    for (int n = t; n < N; n += 256) {
        const float ax = anc[2*n], ay = anc[2*n+1];
        const float dmin = fminf(fminf(ax - gx1, ay - gy1),
                                 fminf(gx2 - ax, gy2 - ay));
        float o = 0.f, al = 0.f;
        if (dmin > 1e-9f) {
            const float4 p = ((const float4*)pb)[b*N + n];
            const float px1 = p.x, py1 = p.y, px2 = p.z, py2 = p.w;
            const float iw = fmaxf(fminf(gx2, px2) - fmaxf(gx1, px1), 0.f);
            const float ih = fmaxf(fminf(gy2, py2) - fmaxf(gy1, py1), 0.f);
            const float inter = iw * ih;
            const float w2 = px2 - px1;
            const float h2 = py2 - py1 + 1e-7f;
            const float uni = w1*h1 + w2*h2 - inter + 1e-7f;
            const float iou = inter / uni;
            const float cw = fmaxf(gx2, px2) - fminf(gx1, px1);
            const float ch = fmaxf(gy2, py2) - fminf(gy1, py1);
            const float c2 = cw*cw + ch*ch + 1e-7f;
            const float dx = px1 + px2 - gx1 - gx2;
            const float dy = py1 + py2 - gy1 - gy2;
            const float rho2 = (dx*dx + dy*dy) * 0.25f;
            const float dat = atanf(w2 / h2) - at1;
            const float v = inv_pi2_4 * dat * dat;
            const float a = v / (v - iou + 1.0f + 1e-7f);
            const float ciou = iou - (rho2 / c2 + v * a);
            o = fmaxf(ciou, 0.f);
            const float s = ps[(b*N + n)*C + cls];
            const float o2 = o * o;
            al = s * (o2 * o2 * o2);   // s^1 * o^6
        }
        orow[n] = o;
        arow[n] = al;
        row[n]  = al;
    }
    __syncthreads();

    // Iterative top-13 block argmax; ties -> lowest index (jax.lax.top_k order).
    for (int k = 0; k < TOPK; k++) {
        float bv = -1.f; int bi = N;
        for (int n = t; n < N; n += 256) {
            const float v = row[n];
            if (v > bv) { bv = v; bi = n; }   // ascending n: equal keeps lower idx
        }
        rv[t] = bv; ri[t] = bi;
        __syncthreads();
        for (int s = 128; s > 0; s >>= 1) {
            if (t < s) {
                const float v2 = rv[t+s]; const int i2 = ri[t+s];
                if (v2 > rv[t] || (v2 == rv[t] && i2 < ri[t])) { rv[t] = v2; ri[t] = i2; }
            }
            __syncthreads();
        }
        if (t == 0) { pick[k] = ri[0]; row[ri[0]] = -1.f; }
        __syncthreads();
    }

    // Scatter: mask_pos = mask_topk & valid  (mask_gt already true here)
    if (t < TOPK) {
        const int n = pick[t];
        const float ax = anc[2*n], ay = anc[2*n+1];
        const float dmin = fminf(fminf(ax - gx1, ay - gy1),
                                 fminf(gx2 - ax, gy2 - ay));
        if (dmin > 1e-9f)
            atomicOr(&g_maskpos[b*N + n], 1u << m);
    }
}

__global__ __launch_bounds__(256) void k_assign(
    const int*   __restrict__ labels,
    const float* __restrict__ gtb,
    float*       __restrict__ out)
{
    const int idx = blockIdx.x * blockDim.x + threadIdx.x;
    if (idx >= B*N) return;
    const int b = idx / N;
    const int n = idx - b * N;

    const unsigned u = g_maskpos[idx];

    // best_gt = argmax over m of overlaps (first max wins ties)
    float bv = -1.f; int bestm = 0;
    const int base = b * M * N + n;
    #pragma unroll
    for (int m = 0; m < M; m++) {
        const float v = g_over[base + m*N];
        if (v > bv) { bv = v; bestm = m; }
    }

    const int fg = __popc(u);
    const unsigned f = (fg > 1) ? (1u << bestm) : u;
    g_maskpos[idx] = f;

    const int tgi = f ? (__ffs((int)f) - 1) : 0;
    const int bmE = b * M + tgi;

    out[L0 + idx] = (float)labels[bmE];
    ((float4*)(out + L1))[idx] = ((const float4*)gtb)[bmE];
    out[L3 + idx] = f ? 1.f : 0.f;
    out[L4 + idx] = (float)tgi;

    if (f) {
        const float a = g_align[bmE*N + n];
        const float o = g_over [bmE*N + n];
        atomicMax((int*)&g_posalign[bmE], __float_as_int(a));
        atomicMax((int*)&g_posover [bmE], __float_as_int(o));
    }
}

__global__ __launch_bounds__(256) void k_scores(
    const int* __restrict__ labels,
    float*     __restrict__ out)
{
    const int idx = blockIdx.x * blockDim.x + threadIdx.x;  // (b,n) * 20 groups
    if (idx >= B*N*(C/4)) return;
    const int rowid = idx / (C/4);
    const int j     = idx - rowid * (C/4);
    const int b = rowid / N;
    const int n = rowid - b * N;

    const unsigned f = g_maskpos[rowid];
    float norm = 0.f; int label = 0;
    if (f) {
        const int m = __ffs((int)f) - 1;
        const int bmE = b * M + m;
        label = labels[bmE];
        const float a = g_align[bmE*N + n];
        norm = a * g_posover[bmE] / (g_posalign[bmE] + 1e-9f);
    }
    float4 v = make_float4(0.f, 0.f, 0.f, 0.f);
    if (f && (label >> 2) == j) ((float*)&v)[label & 3] = norm;
    ((float4*)(out + L2))[idx] = v;
}

extern "C" void kernel_launch(void* const* d_in, const int* in_sizes, int n_in,
                              void* d_out, int out_size) {
    const float* ps     = (const float*)d_in[0];
    const float* pb     = (const float*)d_in[1];
    const float* anc    = (const float*)d_in[2];
    const int*   labels = (const int*)  d_in[3];
    const float* gtb    = (const float*)d_in[4];
    const void*  maskg  =               d_in[5];
    float* out = (float*)d_out;

    k_init<<<(B*N + 255)/256, 256>>>((const unsigned char*)maskg);
    k_rows<<<B*M, 256>>>(ps, pb, anc, labels, gtb, maskg);
    k_assign<<<(B*N + 255)/256, 256>>>(labels, gtb, out);
    k_scores<<<(B*N*(C/4) + 255)/256, 256>>>(labels, out);
}

// round 2
// speedup vs baseline: 1.2999x; 1.2999x over previous
#include <cuda_runtime.h>
#include <cuda_bf16.h>
#include <math_constants.h>

#define B 16
#define N 8400
#define M 32
#define C 80
#define TOPK 13

// Output layout (f32 elements), tuple flattened & concatenated:
#define L0 0                      // target_labels  (B,N)
#define L1 (B*N)                  // target_bboxes  (B,N,4)
#define L2 (L1 + B*N*4)           // target_scores  (B,N,C)
#define L3 (L2 + B*N*C)           // fg_mask        (B,N)
#define L4 (L3 + B*N)             // target_gt_idx  (B,N)

// Scratch (device globals; no runtime allocation)
__device__ float    g_over [B*M*N];
__device__ unsigned g_maskpos[B*N];
__device__ float    g_posalign[B*M];
__device__ float    g_posover [B*M];
__device__ unsigned g_valid[B];
__device__ int      g_mask_is_u8;

// ---------------------------------------------------------------------------
// k_init: zero scratch + zero-fill the target_scores region of the output
// (bulk float4 stores; everything else in out is fully overwritten later).
// Also detects mask_gt dtype (uint8 bool vs int32).
// ---------------------------------------------------------------------------
__global__ __launch_bounds__(256) void k_init(const unsigned char* __restrict__ mask_raw,
                                              float* __restrict__ out) {
    const int i = blockIdx.x * blockDim.x + threadIdx.x;   // 2,688,000 threads
    ((float4*)(out + L2))[i] = make_float4(0.f, 0.f, 0.f, 0.f);
    if (i < B*N) g_maskpos[i] = 0u;
    if (i < B*M) { g_posalign[i] = 0.f; g_posover[i] = 0.f; }
    if (i < B)   g_valid[i] = 0u;
    if (i == 0) {
        int u8 = 0;
        for (int p = 0; p < B*M; p++)
            if ((p & 3) != 0 && mask_raw[p] != 0) u8 = 1;
        g_mask_is_u8 = u8;
    }
}

// ---------------------------------------------------------------------------
// k_rows: one block per (b,m). Computes CIoU row, per-thread top-13 into a
// sorted register list of packed keys, stream-merge to global top-13,
// scatters mask bits. Writes g_over only for valid gt rows.
// Key packing: (float_bits(align) << 32) | (8400 - n)  -> max => value desc,
// ties -> lower n (matches jax.lax.top_k ordering). Keys are unique.
// ---------------------------------------------------------------------------
__global__ __launch_bounds__(256) void k_rows(
    const float* __restrict__ ps,      // pd_scores (B,N,C)
    const float* __restrict__ pb,      // pd_bboxes (B,N,4)
    const float* __restrict__ anc,     // anc_points (N,2)
    const int*   __restrict__ labels,  // gt_labels (B,M,1)
    const float* __restrict__ gtb,     // gt_bboxes (B,M,4)
    const void*  __restrict__ maskg)   // mask_gt (B,M,1)
{
    __shared__ unsigned long long cand[256 * TOPK];
    __shared__ unsigned long long warpred[8];
    __shared__ unsigned long long s_best;
    __shared__ int pick[TOPK];

    const int bm = blockIdx.x;      // b*M + m
    const int b  = bm >> 5;
    const int m  = bm & 31;
    const int t  = threadIdx.x;

    const int mg = g_mask_is_u8 ? (int)((const unsigned char*)maskg)[bm]
                                : ((const int*)maskg)[bm];
    if (!mg) return;
    if (t == 0) atomicOr(&g_valid[b], 1u << m);

    float* __restrict__ orow = g_over + (size_t)bm * N;

    const float4 gt = ((const float4*)gtb)[bm];
    const int cls = labels[bm];
    const float gx1 = gt.x, gy1 = gt.y, gx2 = gt.z, gy2 = gt.w;
    const float w1  = gx2 - gx1;
    const float h1  = gy2 - gy1 + 1e-7f;
    const float at1 = atanf(w1 / h1);
    const float inv_pi2_4 = 4.0f / (CUDART_PI_F * CUDART_PI_F);

    unsigned long long lst[TOPK];
    #pragma unroll
    for (int j = 0; j < TOPK; j++) lst[j] = 0ull;

    for (int n = t; n < N; n += 256) {
        const float2 a2 = ((const float2*)anc)[n];
        const float ax = a2.x, ay = a2.y;
        const float dmin = fminf(fminf(ax - gx1, ay - gy1),
                                 fminf(gx2 - ax, gy2 - ay));
        float o = 0.f, al = 0.f;
        if (dmin > 1e-9f) {
            const float4 p = ((const float4*)pb)[b*N + n];
            const float px1 = p.x, py1 = p.y, px2 = p.z, py2 = p.w;
            const float iw = fmaxf(fminf(gx2, px2) - fmaxf(gx1, px1), 0.f);
            const float ih = fmaxf(fminf(gy2, py2) - fmaxf(gy1, py1), 0.f);
            const float inter = iw * ih;
            const float w2 = px2 - px1;
            const float h2 = py2 - py1 + 1e-7f;
            const float uni = w1*h1 + w2*h2 - inter + 1e-7f;
            const float iou = inter / uni;
            const float cw = fmaxf(gx2, px2) - fminf(gx1, px1);
            const float ch = fmaxf(gy2, py2) - fminf(gy1, py1);
            const float c2 = cw*cw + ch*ch + 1e-7f;
            const float dx = px1 + px2 - gx1 - gx2;
            const float dy = py1 + py2 - gy1 - gy2;
            const float rho2 = (dx*dx + dy*dy) * 0.25f;
            const float dat = atanf(w2 / h2) - at1;
            const float v = inv_pi2_4 * dat * dat;
            const float a = v / (v - iou + 1.0f + 1e-7f);
            const float ciou = iou - (rho2 / c2 + v * a);
            o = fmaxf(ciou, 0.f);
            const float s = ps[(b*N + n)*C + cls];
            const float o2 = o * o;
            al = s * (o2 * o2 * o2);   // s^alpha * o^beta
        }
        orow[n] = o;

        const unsigned long long key =
            ((unsigned long long)__float_as_uint(al) << 32) |
            (unsigned)(N - n);
        if (key > lst[TOPK-1]) {
            lst[TOPK-1] = key;
            #pragma unroll
            for (int j = TOPK-1; j > 0; j--) {
                if (lst[j] > lst[j-1]) {
                    unsigned long long tmp = lst[j-1];
                    lst[j-1] = lst[j]; lst[j] = tmp;
                }
            }
        }
    }

    #pragma unroll
    for (int j = 0; j < TOPK; j++) cand[t*TOPK + j] = lst[j];
    __syncthreads();

    // Stream-merge: 13 rounds of block-argmax over per-thread stream heads.
    const int wid = t >> 5, lane = t & 31;
    int ptr = 0;
    for (int k = 0; k < TOPK; k++) {
        const unsigned long long head = (ptr < TOPK) ? cand[t*TOPK + ptr] : 0ull;
        unsigned long long h = head;
        #pragma unroll
        for (int off = 16; off > 0; off >>= 1) {
            unsigned long long hh = __shfl_xor_sync(0xffffffffu, h, off);
            h = (hh > h) ? hh : h;
        }
        if (lane == 0) warpred[wid] = h;
        __syncthreads();
        if (t == 0) {
            unsigned long long bb = warpred[0];
            #pragma unroll
            for (int i = 1; i < 8; i++) bb = (warpred[i] > bb) ? warpred[i] : bb;
            s_best = bb;
            pick[k] = N - (int)(unsigned)(bb & 0xffffffffull);
        }
        __syncthreads();
        if (head == s_best) ptr++;    // keys unique: exactly one thread advances
    }

    // Scatter: mask_pos = mask_topk & mask_in_gts (mask_gt already true here)
    if (t < TOPK) {
        const int n = pick[t];
        const float2 a2 = ((const float2*)anc)[n];
        const float dmin = fminf(fminf(a2.x - gx1, a2.y - gy1),
                                 fminf(gx2 - a2.x, gy2 - a2.y));
        if (dmin > 1e-9f)
            atomicOr(&g_maskpos[b*N + n], 1u << m);
    }
}

// ---------------------------------------------------------------------------
// k_assign: per (b,n). Resolves multi-assignment via best-overlap, writes
// labels/bboxes/fg/tgi outputs, accumulates per-gt pos_align/pos_over maxima.
// ---------------------------------------------------------------------------
__global__ __launch_bounds__(256) void k_assign(
    const float* __restrict__ ps,
    const int*   __restrict__ labels,
    const float* __restrict__ gtb,
    float*       __restrict__ out)
{
    const int idx = blockIdx.x * blockDim.x + threadIdx.x;
    if (idx >= B*N) return;
    const int b = idx / N;
    const int n = idx - b * N;

    const unsigned u  = g_maskpos[idx];
    const unsigned vm = g_valid[b];

    // best_gt = argmax over m of overlaps (first max wins ties; invalid rows = 0)
    float bv = -1.f; int bestm = 0;
    const int base = b * M * N + n;
    #pragma unroll
    for (int m = 0; m < M; m++) {
        const float v = ((vm >> m) & 1u) ? g_over[base + m*N] : 0.f;
        if (v > bv) { bv = v; bestm = m; }
    }

    const unsigned f = (__popc(u) > 1) ? (1u << bestm) : u;
    g_maskpos[idx] = f;

    const int tgi = f ? (__ffs((int)f) - 1) : 0;
    const int bmE = b * M + tgi;

    out[L0 + idx] = (float)labels[bmE];
    ((float4*)(out + L1))[idx] = ((const float4*)gtb)[bmE];
    out[L3 + idx] = f ? 1.f : 0.f;
    out[L4 + idx] = (float)tgi;

    if (f) {
        const float o  = g_over[bmE*N + n];
        const float s  = ps[(size_t)idx * C + labels[bmE]];
        const float o2 = o * o;
        const float a  = s * (o2 * o2 * o2);
        atomicMax((int*)&g_posalign[bmE], __float_as_int(a));
        atomicMax((int*)&g_posover [bmE], __float_as_int(o));
    }
}

// ---------------------------------------------------------------------------
// k_scatter: sparse write of the single nonzero target_scores element per
// foreground anchor (region pre-zeroed by k_init).
// ---------------------------------------------------------------------------
__global__ __launch_bounds__(256) void k_scatter(
    const float* __restrict__ ps,
    const int*   __restrict__ labels,
    float*       __restrict__ out)
{
    const int idx = blockIdx.x * blockDim.x + threadIdx.x;
    if (idx >= B*N) return;
    const unsigned f = g_maskpos[idx];
    if (!f) return;
    const int b = idx / N;
    const int n = idx - b * N;
    const int m = __ffs((int)f) - 1;
    const int bmE = b * M + m;
    const int lab = labels[bmE];
    const float o  = g_over[bmE*N + n];
    const float s  = ps[(size_t)idx * C + lab];
    const float o2 = o * o;
    const float a  = s * (o2 * o2 * o2);
    const float norm = a * g_posover[bmE] / (g_posalign[bmE] + 1e-9f);
    out[L2 + (size_t)idx * C + lab] = norm;
}

extern "C" void kernel_launch(void* const* d_in, const int* in_sizes, int n_in,
                              void* d_out, int out_size) {
    const float* ps     = (const float*)d_in[0];
    const float* pb     = (const float*)d_in[1];
    const float* anc    = (const float*)d_in[2];
    const int*   labels = (const int*)  d_in[3];
    const float* gtb    = (const float*)d_in[4];
    const void*  maskg  =               d_in[5];
    float* out = (float*)d_out;

    k_init<<<(B*N*C/4 + 255)/256, 256>>>((const unsigned char*)maskg, out);
    k_rows<<<B*M, 256>>>(ps, pb, anc, labels, gtb, maskg);
    k_assign<<<(B*N + 255)/256, 256>>>(ps, labels, gtb, out);
    k_scatter<<<(B*N + 255)/256, 256>>>(ps, labels, out);
}

// round 3
// speedup vs baseline: 1.4850x; 1.1423x over previous
#include <cuda_runtime.h>
#include <cuda_bf16.h>
#include <math_constants.h>

#define B 16
#define N 8400
#define M 32
#define C 80
#define TOPK 13

// Output layout (f32 elements), tuple flattened & concatenated:
#define L0 0                      // target_labels  (B,N)
#define L1 (B*N)                  // target_bboxes  (B,N,4)
#define L2 (L1 + B*N*4)           // target_scores  (B,N,C)
#define L3 (L2 + B*N*C)           // fg_mask        (B,N)
#define L4 (L3 + B*N)             // target_gt_idx  (B,N)

#define ZBLK 171                  // zero-duty blocks inside k_rowsZ
#define GRID_ROWS 684             // bid%4==3 -> zero duty (171), else compute bm (513)

// Scratch (device globals; zero-initialized at load; self-cleaning across calls)
__device__ float    g_over [B*M*N];    // overlaps, valid rows only
__device__ float    g_anorm[B*N];      // stashed align metric for fg anchors
__device__ unsigned g_maskpos[B*N];    // OR-accumulated bits; zeroed by k_scatter
__device__ float    g_posalign[B*M];   // zeroed by zero-duty blocks
__device__ float    g_posover [B*M];
__device__ unsigned g_valid[B];        // zeroed by k_scatter

// ---------------------------------------------------------------------------
// k_rowsZ: grid 684.
//   bid%4==3 : zero-duty — fill out target_scores region + pos arrays with 0.
//   else     : compute block for gt row bm. CIoU row, per-thread top-13 packed
//              keys, stream-merge to global top-13, scatter mask bits.
// Key packing: (float_bits(align) << 32) | (8400 - n): max => value desc,
// ties -> lower n (jax.lax.top_k order). Keys unique.
// ---------------------------------------------------------------------------
__global__ __launch_bounds__(256) void k_rowsZ(
    const float* __restrict__ ps,      // pd_scores (B,N,C)
    const float* __restrict__ pb,      // pd_bboxes (B,N,4)
    const float* __restrict__ anc,     // anc_points (N,2)
    const int*   __restrict__ labels,  // gt_labels (B,M,1)
    const float* __restrict__ gtb,     // gt_bboxes (B,M,4)
    const unsigned char* __restrict__ mask_raw,  // mask_gt (B,M,1), dtype unknown
    float*       __restrict__ out)
{
    const int bid = blockIdx.x;
    const int t   = threadIdx.x;
    const int r   = bid & 3, q = bid >> 2;

    if (r == 3) {   // ---- zero duty ----
        const float4 z4 = make_float4(0.f, 0.f, 0.f, 0.f);
        for (int i = q*256 + t; i < B*N*C/4; i += ZBLK*256)
            ((float4*)(out + L2))[i] = z4;
        if (q == 0) {
            for (int i = t; i < B*M; i += 256) {
                g_posalign[i] = 0.f; g_posover[i] = 0.f;
            }
        }
        return;
    }

    const int bm = q*3 + r;
    if (bm >= B*M) return;
    const int b  = bm >> 5;
    const int m  = bm & 31;

    // Detect mask_gt dtype (uint8 bool vs int32): int32 {0,1} has zero bytes
    // at offsets p%4!=0. Block-uniform result.
    int bad = 0;
    for (int p = t; p < 512; p += 256)
        if ((p & 3) != 0 && mask_raw[p] != 0) bad = 1;
    const int is_u8 = __syncthreads_or(bad);

    const int mg = is_u8 ? (int)mask_raw[bm] : ((const int*)mask_raw)[bm];
    if (!mg) return;
    if (t == 0) atomicOr(&g_valid[b], 1u << m);

    __shared__ unsigned long long cand[256 * TOPK];
    __shared__ unsigned long long warpred[8];
    __shared__ unsigned long long s_best;
    __shared__ int pick[TOPK];

    float* __restrict__ orow = g_over + (size_t)bm * N;

    const float4 gt = ((const float4*)gtb)[bm];
    const int cls = labels[bm];
    const float gx1 = gt.x, gy1 = gt.y, gx2 = gt.z, gy2 = gt.w;
    const float w1  = gx2 - gx1;
    const float h1  = gy2 - gy1 + 1e-7f;
    const float at1 = atanf(w1 / h1);
    const float inv_pi2_4 = 4.0f / (CUDART_PI_F * CUDART_PI_F);

    unsigned long long lst[TOPK];
    #pragma unroll
    for (int j = 0; j < TOPK; j++) lst[j] = 0ull;

    for (int n = t; n < N; n += 256) {
        const float2 a2 = ((const float2*)anc)[n];
        const float ax = a2.x, ay = a2.y;
        const float dmin = fminf(fminf(ax - gx1, ay - gy1),
                                 fminf(gx2 - ax, gy2 - ay));
        float o = 0.f, al = 0.f;
        if (dmin > 1e-9f) {
            const float4 p = ((const float4*)pb)[b*N + n];
            const float px1 = p.x, py1 = p.y, px2 = p.z, py2 = p.w;
            const float iw = fmaxf(fminf(gx2, px2) - fmaxf(gx1, px1), 0.f);
            const float ih = fmaxf(fminf(gy2, py2) - fmaxf(gy1, py1), 0.f);
            const float inter = iw * ih;
            const float w2 = px2 - px1;
            const float h2 = py2 - py1 + 1e-7f;
            const float uni = w1*h1 + w2*h2 - inter + 1e-7f;
            const float iou = inter / uni;
            const float cw = fmaxf(gx2, px2) - fminf(gx1, px1);
            const float ch = fmaxf(gy2, py2) - fminf(gy1, py1);
            const float c2 = cw*cw + ch*ch + 1e-7f;
            const float dx = px1 + px2 - gx1 - gx2;
            const float dy = py1 + py2 - gy1 - gy2;
            const float rho2 = (dx*dx + dy*dy) * 0.25f;
            const float dat = atanf(w2 / h2) - at1;
            const float v = inv_pi2_4 * dat * dat;
            const float a = v / (v - iou + 1.0f + 1e-7f);
            const float ciou = iou - (rho2 / c2 + v * a);
            o = fmaxf(ciou, 0.f);
            const float s = ps[(b*N + n)*C + cls];
            const float o2 = o * o;
            al = s * (o2 * o2 * o2);   // s^alpha * o^beta
        }
        orow[n] = o;

        const unsigned long long key =
            ((unsigned long long)__float_as_uint(al) << 32) |
            (unsigned)(N - n);
        if (key > lst[TOPK-1]) {
            lst[TOPK-1] = key;
            #pragma unroll
            for (int j = TOPK-1; j > 0; j--) {
                if (lst[j] > lst[j-1]) {
                    unsigned long long tmp = lst[j-1];
                    lst[j-1] = lst[j]; lst[j] = tmp;
                }
            }
        }
    }

    #pragma unroll
    for (int j = 0; j < TOPK; j++) cand[t*TOPK + j] = lst[j];
    __syncthreads();

    // Stream-merge: 13 rounds of block-argmax over per-thread stream heads.
    const int wid = t >> 5, lane = t & 31;
    int ptr = 0;
    for (int k = 0; k < TOPK; k++) {
        const unsigned long long head = (ptr < TOPK) ? cand[t*TOPK + ptr] : 0ull;
        unsigned long long h = head;
        #pragma unroll
        for (int off = 16; off > 0; off >>= 1) {
            unsigned long long hh = __shfl_xor_sync(0xffffffffu, h, off);
            h = (hh > h) ? hh : h;
        }
        if (lane == 0) warpred[wid] = h;
        __syncthreads();
        if (t == 0) {
            unsigned long long bb = warpred[0];
            #pragma unroll
            for (int i = 1; i < 8; i++) bb = (warpred[i] > bb) ? warpred[i] : bb;
            s_best = bb;
            pick[k] = N - (int)(unsigned)(bb & 0xffffffffull);
        }
        __syncthreads();
        if (head == s_best) ptr++;    // keys unique: exactly one thread advances
    }

    // Scatter: mask_pos = mask_topk & mask_in_gts (mask_gt already true here)
    if (t < TOPK) {
        const int n = pick[t];
        const float2 a2 = ((const float2*)anc)[n];
        const float dmin = fminf(fminf(a2.x - gx1, a2.y - gy1),
                                 fminf(gx2 - a2.x, gy2 - a2.y));
        if (dmin > 1e-9f)
            atomicOr(&g_maskpos[b*N + n], 1u << m);
    }
}

// ---------------------------------------------------------------------------
// k_assign: per (b,n). Resolves multi-assignment (argmax scan only if some
// lane in the warp actually needs it), writes labels/bboxes/fg/tgi outputs,
// stashes align metric, accumulates per-gt pos maxima.
// ---------------------------------------------------------------------------
__global__ __launch_bounds__(256) void k_assign(
    const float* __restrict__ ps,
    const int*   __restrict__ labels,
    const float* __restrict__ gtb,
    float*       __restrict__ out)
{
    const int idx = blockIdx.x * 256 + threadIdx.x;   // grid exactly B*N/256
    const int b = idx / N;
    const int n = idx - b * N;

    const unsigned u  = g_maskpos[idx];
    const unsigned vm = g_valid[b];
    const bool multi  = __popc(u) > 1;

    int bestm = 0;
    if (__ballot_sync(0xffffffffu, multi)) {
        // best_gt = argmax over m of overlaps (first max wins; invalid rows 0)
        float bv = -1.f;
        const int base = b * M * N + n;
        #pragma unroll
        for (int m = 0; m < M; m++) {
            const float v = ((vm >> m) & 1u) ? g_over[base + m*N] : 0.f;
            if (v > bv) { bv = v; bestm = m; }
        }
    }

    const unsigned f = multi ? (1u << bestm) : u;
    g_maskpos[idx] = f;

    const int tgi = f ? (__ffs((int)f) - 1) : 0;
    const int bmE = b * M + tgi;
    const int lab = labels[bmE];

    out[L0 + idx] = (float)lab;
    ((float4*)(out + L1))[idx] = ((const float4*)gtb)[bmE];
    out[L3 + idx] = f ? 1.f : 0.f;
    out[L4 + idx] = (float)tgi;

    if (f) {
        const float o  = g_over[bmE*N + n];
        const float s  = ps[(size_t)idx * C + lab];
        const float o2 = o * o;
        const float a  = s * (o2 * o2 * o2);
        g_anorm[idx] = a;
        atomicMax((int*)&g_posalign[bmE], __float_as_int(a));
        atomicMax((int*)&g_posover [bmE], __float_as_int(o));
    }
}

// ---------------------------------------------------------------------------
// k_scatter: sparse write of the single nonzero target_scores element per
// foreground anchor; also self-cleans g_maskpos / g_valid for the next call.
// ---------------------------------------------------------------------------
__global__ __launch_bounds__(256) void k_scatter(
    const int* __restrict__ labels,
    float*     __restrict__ out)
{
    const int idx = blockIdx.x * 256 + threadIdx.x;
    const unsigned f = g_maskpos[idx];
    g_maskpos[idx] = 0u;                 // self-clean for next call
    if (idx < B) g_valid[idx] = 0u;
    if (!f) return;
    const int b = idx / N;
    const int m = __ffs((int)f) - 1;
    const int bmE = b * M + m;
    const float a = g_anorm[idx];
    const float norm = a * g_posover[bmE] / (g_posalign[bmE] + 1e-9f);
    out[L2 + (size_t)idx * C + labels[bmE]] = norm;
}

extern "C" void kernel_launch(void* const* d_in, const int* in_sizes, int n_in,
                              void* d_out, int out_size) {
    const float* ps     = (const float*)d_in[0];
    const float* pb     = (const float*)d_in[1];
    const float* anc    = (const float*)d_in[2];
    const int*   labels = (const int*)  d_in[3];
    const float* gtb    = (const float*)d_in[4];
    const unsigned char* maskg = (const unsigned char*)d_in[5];
    float* out = (float*)d_out;

    k_rowsZ<<<GRID_ROWS, 256>>>(ps, pb, anc, labels, gtb, maskg, out);
    k_assign<<<(B*N)/256, 256>>>(ps, labels, gtb, out);
    k_scatter<<<(B*N)/256, 256>>>(labels, out);
}